// round 14
// baseline (speedup 1.0000x reference)
#include <cuda_runtime.h>
#include <cuda_fp16.h>
#include <cstdint>
#include <math.h>

// ---------------- problem constants ----------------
#define NMAX   20000
#define EMAX   400000
#define RREL   8
#define HDIM   256
#define ODIM   128

// GEMM tiling (fp16 mma m16n8k16)
#define BM 128
#define BN 128
#define KDIM 256
#define KC 32                    // K halves per smem chunk (= 64 B/row)
#define NKC (KDIM/KC)            // 8 chunks
#define HSTRIDE 40               // padded smem row stride in halves (conflict-free)
#define CHUNK_H (128*HSTRIDE)
#define SMEM_BYTES (4*CHUNK_H*2) // A0,A1,B0,B1 = 40960 B

// ---------------- static scratch ----------------
__device__ __align__(16) __half g_hrh[(size_t)NMAX * RREL * HDIM];  // relation blocks, fp16
__device__ __align__(16) float  g_root[(size_t)NMAX * HDIM];        // root block, fp32
__device__ __align__(16) float  g_h1[(size_t)NMAX * HDIM];
__device__ __align__(16) float  g_h2[(size_t)NMAX * HDIM];
__device__ __align__(16) __half g_arth[(size_t)NMAX * HDIM];        // fp16 activations (GEMM A)
__device__ __align__(16) float  g_relagg[(size_t)NMAX * HDIM];
__device__ __align__(16) __half g_wcat[(size_t)(9*HDIM) * KDIM];    // B K-major fp16
__device__ float g_projrel[RREL * HDIM];
__device__ float g_sc[NMAX * 9];
__device__ float g_score[EMAX];    // CSR-ordered leaky scores
__device__ int   g_rbb[EMAX];      // CSR-ordered src*8+et
__device__ int   g_dn[EMAX];       // CSR-ordered dst node
__device__ int   g_deg[NMAX];
__device__ int   g_rowptr[NMAX + 1];
__device__ int   g_cursor[NMAX];
__device__ int   g_cnt[NMAX * RREL];

// ---------------- helpers ----------------
__device__ __forceinline__ uint32_t smem_u32(const void* p) {
    uint32_t a;
    asm("{ .reg .u64 t; cvta.to.shared.u64 t, %1; cvt.u32.u64 %0, t; }" : "=r"(a) : "l"(p));
    return a;
}
__device__ __forceinline__ void cp_async16(uint32_t dst, const void* src, int src_sz) {
    asm volatile("cp.async.ca.shared.global [%0], [%1], 16, %2;"
                 :: "r"(dst), "l"(src), "r"(src_sz) : "memory");
}
__device__ __forceinline__ void mma_f16(float& d0, float& d1, float& d2, float& d3,
                                        uint32_t a0, uint32_t a1, uint32_t a2, uint32_t a3,
                                        uint32_t b0, uint32_t b1) {
    asm volatile(
        "mma.sync.aligned.m16n8k16.row.col.f32.f16.f16.f32 "
        "{%0,%1,%2,%3}, {%4,%5,%6,%7}, {%8,%9}, {%0,%1,%2,%3};"
        : "+f"(d0), "+f"(d1), "+f"(d2), "+f"(d3)
        : "r"(a0), "r"(a1), "r"(a2), "r"(a3), "r"(b0), "r"(b1));
}

// ---------------- prep kernels ----------------
__global__ void k_zero() {
    int i = blockIdx.x * blockDim.x + threadIdx.x;
    if (i < NMAX) g_deg[i] = 0;
    if (i < NMAX * RREL) g_cnt[i] = 0;
}
__global__ void k_degcnt(const int* __restrict__ dst, const int* __restrict__ et, int E) {
    int e = blockIdx.x * blockDim.x + threadIdx.x;
    if (e < E) {
        int d = dst[e];
        atomicAdd(&g_deg[d], 1);
        atomicAdd(&g_cnt[d * RREL + et[e]], 1);
    }
}
__global__ void k_scan(int n) {
    __shared__ int part[1024];
    int t = threadIdx.x;
    int per = (n + 1023) >> 10;
    int base = t * per;
    int s = 0;
    for (int i = 0; i < per; i++) { int idx = base + i; if (idx < n) s += g_deg[idx]; }
    part[t] = s; __syncthreads();
    for (int off = 1; off < 1024; off <<= 1) {
        int v = (t >= off) ? part[t - off] : 0;
        __syncthreads(); part[t] += v; __syncthreads();
    }
    int run = (t > 0) ? part[t - 1] : 0;
    for (int i = 0; i < per; i++) {
        int idx = base + i;
        if (idx < n) { g_rowptr[idx] = run; g_cursor[idx] = run; run += g_deg[idx]; }
    }
    if (t == 1023) g_rowptr[n] = part[1023];
}
// CSR fill: store src*8+et and dst per CSR slot
__global__ void k_fill(const int* __restrict__ src, const int* __restrict__ dst,
                       const int* __restrict__ et, int E) {
    int e = blockIdx.x * blockDim.x + threadIdx.x;
    if (e < E) {
        int d = dst[e];
        int p = atomicAdd(&g_cursor[d], 1);
        g_rbb[p] = src[e] * RREL + et[e];
        g_dn[p]  = d;
    }
}
__global__ void k_projrel(const float* __restrict__ re, const float* __restrict__ w,
                          const float* __restrict__ b) {
    int r = blockIdx.x, c = threadIdx.x;
    float s = b[c];
    for (int k = 0; k < HDIM; k++) s += re[r * HDIM + k] * w[k * HDIM + c];
    g_projrel[r * HDIM + c] = s;
}
__global__ void k_relagg() {
    int node = blockIdx.x, c = threadIdx.x;
    __shared__ float cc[RREL];
    if (c < RREL) cc[c] = (float)g_cnt[node * RREL + c];
    __syncthreads();
    float s = 0.f;
#pragma unroll
    for (int r = 0; r < RREL; r++) s += cc[r] * g_projrel[r * HDIM + c];
    g_relagg[(size_t)node * HDIM + c] = s;
}
// transpose weights K-major fp16 (z<9); z==9 slice zeroes g_sc for this layer.
__global__ void k_repackT(const float* __restrict__ Wr, const float* __restrict__ Wo,
                          int dob, int n9) {
    int j = blockIdx.z;
    if (j == 9) {
        int nb = gridDim.x * gridDim.y;
        int bid = blockIdx.y * gridDim.x + blockIdx.x;
        int t0 = bid * 256 + threadIdx.y * 32 + threadIdx.x;
        for (int i = t0; i < n9; i += nb * 256) g_sc[i] = 0.f;
        return;
    }
    __shared__ float t[32][33];
    int k0 = blockIdx.y * 32, c0 = blockIdx.x * 32;
    const float* W = (j < RREL) ? Wr + (size_t)j * KDIM * dob : Wo;
    for (int r = threadIdx.y; r < 32; r += 8)
        t[r][threadIdx.x] = W[(size_t)(k0 + r) * dob + c0 + threadIdx.x];
    __syncthreads();
    for (int r = threadIdx.y; r < 32; r += 8) {
        int n = j * dob + c0 + r;
        g_wcat[(size_t)n * KDIM + k0 + threadIdx.x] = __float2half_rn(t[threadIdx.x][r]);
    }
}
__global__ void k_tohalf(const float* __restrict__ in, __half* __restrict__ out, int n4) {
    int i = blockIdx.x * blockDim.x + threadIdx.x;
    if (i >= n4) return;
    float4 v = ((const float4*)in)[i];
    ((__half2*)out)[i * 2]     = __floats2half2_rn(v.x, v.y);
    ((__half2*)out)[i * 2 + 1] = __floats2half2_rn(v.z, v.w);
}

// ---------------- fp16 mma GEMM + fused attention-dot + split fp16/fp32 store ----------------
__global__ __launch_bounds__(256, 2)
void k_mma(const __half* __restrict__ A, __half* __restrict__ Ch, float* __restrict__ Cr,
           int M, int dob,
           const float* __restrict__ asrc, const float* __restrict__ adst) {
    extern __shared__ __half sm[];
    __half* sA[2] = { sm,               sm + CHUNK_H };
    __half* sB[2] = { sm + 2 * CHUNK_H, sm + 3 * CHUNK_H };

    int tid  = threadIdx.x;
    int wid  = tid >> 5, lane = tid & 31;
    int wm   = wid >> 1;
    int wn   = wid & 1;
    int bm   = blockIdx.y * BM, bn = blockIdx.x * BN;
    int lq   = lane >> 2;
    int lr   = lane & 3;

    float acc[2][8][4];
#pragma unroll
    for (int mt = 0; mt < 2; mt++)
#pragma unroll
        for (int nt = 0; nt < 8; nt++)
#pragma unroll
            for (int i = 0; i < 4; i++) acc[mt][nt][i] = 0.f;

    uint32_t sAb[2] = { smem_u32(sA[0]), smem_u32(sA[1]) };
    uint32_t sBb[2] = { smem_u32(sB[0]), smem_u32(sB[1]) };

    int lrow = tid >> 1;          // 0..127
    int lseg = (tid & 1) * 16;    // 0 or 16 halves
    int asz  = (bm + lrow < M) ? 16 : 0;   // invariant over chunks

    auto load_chunk = [&](int buf, int kc) {
        int c0 = kc * KC;
        const __half* ga = A + (size_t)(bm + lrow) * KDIM + c0 + lseg;
        const __half* gb = g_wcat + (size_t)(bn + lrow) * KDIM + c0 + lseg;
        uint32_t off = (uint32_t)(lrow * HSTRIDE + lseg) * 2u;
        cp_async16(sAb[buf] + off,      ga,     asz);
        cp_async16(sAb[buf] + off + 16, ga + 8, asz);
        cp_async16(sBb[buf] + off,      gb,     16);
        cp_async16(sBb[buf] + off + 16, gb + 8, 16);
        asm volatile("cp.async.commit_group;" ::: "memory");
    };

    load_chunk(0, 0);

    for (int kc = 0; kc < NKC; kc++) {
        int buf = kc & 1;
        if (kc + 1 < NKC) {
            load_chunk(buf ^ 1, kc + 1);
            asm volatile("cp.async.wait_group 1;" ::: "memory");
        } else {
            asm volatile("cp.async.wait_group 0;" ::: "memory");
        }
        __syncthreads();

        const __half* a_s = sA[buf];
        const __half* b_s = sB[buf];
#pragma unroll
        for (int ks = 0; ks < 2; ks++) {
            int kb = ks * 16 + 2 * lr;
            uint32_t afr[2][4];
#pragma unroll
            for (int mt = 0; mt < 2; mt++) {
                int r0 = wm * 32 + mt * 16 + lq;
                afr[mt][0] = *(const uint32_t*)(a_s + r0 * HSTRIDE + kb);
                afr[mt][1] = *(const uint32_t*)(a_s + (r0 + 8) * HSTRIDE + kb);
                afr[mt][2] = *(const uint32_t*)(a_s + r0 * HSTRIDE + kb + 8);
                afr[mt][3] = *(const uint32_t*)(a_s + (r0 + 8) * HSTRIDE + kb + 8);
            }
            uint32_t bfr[8][2];
#pragma unroll
            for (int nt = 0; nt < 8; nt++) {
                int n0 = wn * 64 + nt * 8 + lq;
                bfr[nt][0] = *(const uint32_t*)(b_s + n0 * HSTRIDE + kb);
                bfr[nt][1] = *(const uint32_t*)(b_s + n0 * HSTRIDE + kb + 8);
            }
#pragma unroll
            for (int mt = 0; mt < 2; mt++)
#pragma unroll
                for (int nt = 0; nt < 8; nt++)
                    mma_f16(acc[mt][nt][0], acc[mt][nt][1], acc[mt][nt][2], acc[mt][nt][3],
                            afr[mt][0], afr[mt][1], afr[mt][2], afr[mt][3],
                            bfr[nt][0], bfr[nt][1]);
        }
        if (kc + 1 < NKC) __syncthreads();   // last iteration: nothing after reads smem
    }

    // fused attention-dot + split store
    int j    = bn / dob;               // relation slot (8 = root)
    int cbas = bn - j * dob;
    const float* att = (j < RREL) ? asrc : adst;
    bool isroot = (j >= RREL);

#pragma unroll
    for (int mt = 0; mt < 2; mt++) {
        int r0 = bm + wm * 32 + mt * 16 + lq;
        float s0 = 0.f, s1 = 0.f;
#pragma unroll
        for (int nt = 0; nt < 8; nt++) {
            int col = cbas + wn * 64 + nt * 8 + 2 * lr;
            float a0 = att[col], a1 = att[col + 1];
            s0 += acc[mt][nt][0] * a0 + acc[mt][nt][1] * a1;
            s1 += acc[mt][nt][2] * a0 + acc[mt][nt][3] * a1;
            if (isroot) {
                if (r0 < M)
                    *(float2*)(Cr + (size_t)r0 * dob + col) =
                        make_float2(acc[mt][nt][0], acc[mt][nt][1]);
                if (r0 + 8 < M)
                    *(float2*)(Cr + (size_t)(r0 + 8) * dob + col) =
                        make_float2(acc[mt][nt][2], acc[mt][nt][3]);
            } else {
                if (r0 < M)
                    *(__half2*)(Ch + ((size_t)r0 * RREL + j) * dob + col) =
                        __floats2half2_rn(acc[mt][nt][0], acc[mt][nt][1]);
                if (r0 + 8 < M)
                    *(__half2*)(Ch + ((size_t)(r0 + 8) * RREL + j) * dob + col) =
                        __floats2half2_rn(acc[mt][nt][2], acc[mt][nt][3]);
            }
        }
        s0 += __shfl_xor_sync(0xffffffffu, s0, 1);
        s0 += __shfl_xor_sync(0xffffffffu, s0, 2);
        s1 += __shfl_xor_sync(0xffffffffu, s1, 1);
        s1 += __shfl_xor_sync(0xffffffffu, s1, 2);
        if (lr == 0) {
            if (r0 < M)     atomicAdd(&g_sc[r0 * 9 + j], s0);
            if (r0 + 8 < M) atomicAdd(&g_sc[(r0 + 8) * 9 + j], s1);
        }
    }
}

// ---------------- edge scores, CSR-ordered ----------------
__global__ void k_score(int E) {
    int p = blockIdx.x * blockDim.x + threadIdx.x;
    if (p >= E) return;
    int rbb = g_rbb[p];
    int dn  = g_dn[p];
    float s = g_sc[rbb + (rbb >> 3)] + g_sc[dn * 9 + 8];
    g_score[p] = (s > 0.f) ? s : 0.2f * s;
}

// ---------------- warp-per-node softmax aggregation + epilogue ----------------
// NV=2: dob=256, hidden layers. NV=1: dob=128, final layer.
template <int NV>
__global__ void k_agg(const __half* __restrict__ hrh, const float* __restrict__ root,
                      const float* __restrict__ h_in,
                      float* __restrict__ h_out, __half* __restrict__ arth, int n) {
    int gw = (blockIdx.x * blockDim.x + threadIdx.x) >> 5;
    int lane = threadIdx.x & 31;
    if (gw >= n) return;
    const int dob = NV * 128;
    int node = gw;
    int beg = g_rowptr[node];
    int deg = g_rowptr[node + 1] - beg;

    float accA[4 * NV], accB[4 * NV];
#pragma unroll
    for (int i = 0; i < 4 * NV; i++) { accA[i] = 0.f; accB[i] = 0.f; }

    if (deg > 0) {
        // pass 1: max over CSR-ordered scores (coalesced)
        float m = -1e30f;
        for (int i = lane; i < deg; i += 32)
            m = fmaxf(m, g_score[beg + i]);
#pragma unroll
        for (int o = 16; o; o >>= 1) m = fmaxf(m, __shfl_xor_sync(0xffffffffu, m, o));

        // pass 2: weights (coalesced) + 4-deep unrolled gather (2 acc sets)
        float dsum = 0.f;
        for (int base = 0; base < deg; base += 32) {
            int i = base + lane;
            float wv = 0.f; int rb = 0;
            if (i < deg) {
                wv = __expf(g_score[beg + i] - m);
                rb = g_rbb[beg + i] * dob;
            }
            dsum += wv;
            int cnt = min(32, deg - base);
            int jj = 0;
            for (; jj + 3 < cnt; jj += 4) {
                float w0 = __shfl_sync(0xffffffffu, wv, jj);
                int   r0 = __shfl_sync(0xffffffffu, rb, jj);
                float w1 = __shfl_sync(0xffffffffu, wv, jj + 1);
                int   r1 = __shfl_sync(0xffffffffu, rb, jj + 1);
                float w2 = __shfl_sync(0xffffffffu, wv, jj + 2);
                int   r2 = __shfl_sync(0xffffffffu, rb, jj + 2);
                float w3 = __shfl_sync(0xffffffffu, wv, jj + 3);
                int   r3 = __shfl_sync(0xffffffffu, rb, jj + 3);
                if (NV == 2) {
                    uint4 v0 = ((const uint4*)(hrh + r0))[lane];
                    uint4 v1 = ((const uint4*)(hrh + r1))[lane];
                    uint4 v2 = ((const uint4*)(hrh + r2))[lane];
                    uint4 v3 = ((const uint4*)(hrh + r3))[lane];
                    float2 f;
                    f = __half22float2(*(__half2*)&v0.x); accA[0] += w0*f.x; accA[1] += w0*f.y;
                    f = __half22float2(*(__half2*)&v0.y); accA[2] += w0*f.x; accA[3] += w0*f.y;
                    f = __half22float2(*(__half2*)&v0.z); accA[4] += w0*f.x; accA[5] += w0*f.y;
                    f = __half22float2(*(__half2*)&v0.w); accA[6] += w0*f.x; accA[7] += w0*f.y;
                    f = __half22float2(*(__half2*)&v1.x); accB[0] += w1*f.x; accB[1] += w1*f.y;
                    f = __half22float2(*(__half2*)&v1.y); accB[2] += w1*f.x; accB[3] += w1*f.y;
                    f = __half22float2(*(__half2*)&v1.z); accB[4] += w1*f.x; accB[5] += w1*f.y;
                    f = __half22float2(*(__half2*)&v1.w); accB[6] += w1*f.x; accB[7] += w1*f.y;
                    f = __half22float2(*(__half2*)&v2.x); accA[0] += w2*f.x; accA[1] += w2*f.y;
                    f = __half22float2(*(__half2*)&v2.y); accA[2] += w2*f.x; accA[3] += w2*f.y;
                    f = __half22float2(*(__half2*)&v2.z); accA[4] += w2*f.x; accA[5] += w2*f.y;
                    f = __half22float2(*(__half2*)&v2.w); accA[6] += w2*f.x; accA[7] += w2*f.y;
                    f = __half22float2(*(__half2*)&v3.x); accB[0] += w3*f.x; accB[1] += w3*f.y;
                    f = __half22float2(*(__half2*)&v3.y); accB[2] += w3*f.x; accB[3] += w3*f.y;
                    f = __half22float2(*(__half2*)&v3.z); accB[4] += w3*f.x; accB[5] += w3*f.y;
                    f = __half22float2(*(__half2*)&v3.w); accB[6] += w3*f.x; accB[7] += w3*f.y;
                } else {
                    uint2 v0 = ((const uint2*)(hrh + r0))[lane];
                    uint2 v1 = ((const uint2*)(hrh + r1))[lane];
                    uint2 v2 = ((const uint2*)(hrh + r2))[lane];
                    uint2 v3 = ((const uint2*)(hrh + r3))[lane];
                    float2 f;
                    f = __half22float2(*(__half2*)&v0.x); accA[0] += w0*f.x; accA[1] += w0*f.y;
                    f = __half22float2(*(__half2*)&v0.y); accA[2] += w0*f.x; accA[3] += w0*f.y;
                    f = __half22float2(*(__half2*)&v1.x); accB[0] += w1*f.x; accB[1] += w1*f.y;
                    f = __half22float2(*(__half2*)&v1.y); accB[2] += w1*f.x; accB[3] += w1*f.y;
                    f = __half22float2(*(__half2*)&v2.x); accA[0] += w2*f.x; accA[1] += w2*f.y;
                    f = __half22float2(*(__half2*)&v2.y); accA[2] += w2*f.x; accA[3] += w2*f.y;
                    f = __half22float2(*(__half2*)&v3.x); accB[0] += w3*f.x; accB[1] += w3*f.y;
                    f = __half22float2(*(__half2*)&v3.y); accB[2] += w3*f.x; accB[3] += w3*f.y;
                }
            }
            for (; jj < cnt; jj++) {
                float w0 = __shfl_sync(0xffffffffu, wv, jj);
                int   r0 = __shfl_sync(0xffffffffu, rb, jj);
                if (NV == 2) {
                    uint4 v0 = ((const uint4*)(hrh + r0))[lane];
                    float2 f;
                    f = __half22float2(*(__half2*)&v0.x); accA[0] += w0*f.x; accA[1] += w0*f.y;
                    f = __half22float2(*(__half2*)&v0.y); accA[2] += w0*f.x; accA[3] += w0*f.y;
                    f = __half22float2(*(__half2*)&v0.z); accA[4] += w0*f.x; accA[5] += w0*f.y;
                    f = __half22float2(*(__half2*)&v0.w); accA[6] += w0*f.x; accA[7] += w0*f.y;
                } else {
                    uint2 v0 = ((const uint2*)(hrh + r0))[lane];
                    float2 f;
                    f = __half22float2(*(__half2*)&v0.x); accA[0] += w0*f.x; accA[1] += w0*f.y;
                    f = __half22float2(*(__half2*)&v0.y); accA[2] += w0*f.x; accA[3] += w0*f.y;
                }
            }
        }
#pragma unroll
        for (int o = 16; o; o >>= 1) dsum += __shfl_xor_sync(0xffffffffu, dsum, o);
        float inv = 1.f / dsum;
#pragma unroll
        for (int i = 0; i < 4 * NV; i++) accA[i] = (accA[i] + accB[i]) * inv;
    }

    const float4* rootp = (const float4*)(root + (size_t)node * dob);
    if (NV == 1) {
        float4 r = rootp[lane];
        r.x += accA[0]; r.y += accA[1]; r.z += accA[2]; r.w += accA[3];
        ((float4*)(h_out + (size_t)node * dob))[lane] = r;
    } else {
        const float4* rap = (const float4*)(g_relagg + (size_t)node * HDIM);
        const float4* hip = (const float4*)(h_in + (size_t)node * dob);
        float4* hop = (float4*)(h_out + (size_t)node * dob);
        __half2* arp = (__half2*)(arth + (size_t)node * dob);
#pragma unroll
        for (int q = 0; q < 2; q++) {
            int li = lane * 2 + q;            // float4 index; columns li*4..+4
            float4 r = rootp[li], ra = rap[li], hi = hip[li];
            float4 o;
            o.x = hi.x + fmaxf(r.x + accA[q*4+0] + ra.x, 0.f);
            o.y = hi.y + fmaxf(r.y + accA[q*4+1] + ra.y, 0.f);
            o.z = hi.z + fmaxf(r.z + accA[q*4+2] + ra.z, 0.f);
            o.w = hi.w + fmaxf(r.w + accA[q*4+3] + ra.w, 0.f);
            hop[li] = o;
            arp[li * 2]     = __floats2half2_rn(o.x, o.y);
            arp[li * 2 + 1] = __floats2half2_rn(o.z, o.w);
        }
    }
}

// ---------------- launcher ----------------
extern "C" void kernel_launch(void* const* d_in, const int* in_sizes, int n_in,
                              void* d_out, int out_size) {
    const float* x    = (const float*)d_in[0];
    const int*   ei   = (const int*)  d_in[1];
    const int*   et   = (const int*)  d_in[2];
    const float* remb = (const float*)d_in[3];
    const float* rpw  = (const float*)d_in[4];
    const float* rpb  = (const float*)d_in[5];
    const float* Wr[3] = {(const float*)d_in[6],  (const float*)d_in[10], (const float*)d_in[14]};
    const float* Wo[3] = {(const float*)d_in[7],  (const float*)d_in[11], (const float*)d_in[15]};
    const float* Av[3] = {(const float*)d_in[8],  (const float*)d_in[12], (const float*)d_in[16]};
    const float* Ad[3] = {(const float*)d_in[9],  (const float*)d_in[13], (const float*)d_in[17]};

    int N = in_sizes[0] / HDIM;     // 20000
    int E = in_sizes[2];            // 400000
    const int* srcp = ei;
    const int* dstp = ei + E;

    float *root, *h1, *h2;
    __half *arth, *hrh;
    cudaGetSymbolAddress((void**)&hrh,  g_hrh);
    cudaGetSymbolAddress((void**)&root, g_root);
    cudaGetSymbolAddress((void**)&h1,   g_h1);
    cudaGetSymbolAddress((void**)&h2,   g_h2);
    cudaGetSymbolAddress((void**)&arth, g_arth);

    cudaFuncSetAttribute(k_mma, cudaFuncAttributeMaxDynamicSharedMemorySize, SMEM_BYTES);

    // ---- graph prep (layer-invariant) ----
    k_zero<<<(NMAX * RREL + 255) / 256, 256>>>();
    k_degcnt<<<(E + 255) / 256, 256>>>(dstp, et, E);
    k_scan<<<1, 1024>>>(N);
    k_fill<<<(E + 255) / 256, 256>>>(srcp, dstp, et, E);
    k_projrel<<<RREL, HDIM>>>(remb, rpw, rpb);
    k_relagg<<<N, HDIM>>>();
    int n4 = N * HDIM / 4;
    k_tohalf<<<(n4 + 255) / 256, 256>>>(x, arth, n4);

    // ---- three RGAT layers ----
    const float* hin = x;
    for (int l = 0; l < 3; l++) {
        int dob = (l == 2) ? ODIM : HDIM;
        int pitch = 9 * dob;

        // z slices 0..8: weight repack; z slice 9: zero g_sc
        dim3 gt(dob / 32, KDIM / 32, 10);
        k_repackT<<<gt, dim3(32, 8)>>>(Wr[l], Wo[l], dob, N * 9);

        dim3 g(pitch / BN, (N + BM - 1) / BM);
        k_mma<<<g, 256, SMEM_BYTES>>>(arth, hrh, root, N, dob, Av[l], Ad[l]);

        k_score<<<(E + 255) / 256, 256>>>(E);

        float* hout = (l == 0) ? h1 : (l == 1) ? h2 : (float*)d_out;
        int wblocks = (N * 32 + 255) / 256;
        if (l == 2)
            k_agg<1><<<wblocks, 256>>>(hrh, root, hin, hout, arth, N);
        else
            k_agg<2><<<wblocks, 256>>>(hrh, root, hin, hout, arth, N);
        hin = hout;
    }
}

// round 15
// speedup vs baseline: 1.0393x; 1.0393x over previous
#include <cuda_runtime.h>
#include <cuda_fp16.h>
#include <cstdint>
#include <math.h>

// ---------------- problem constants ----------------
#define NMAX   20000
#define EMAX   400000
#define RREL   8
#define HDIM   256
#define ODIM   128

// GEMM tiling (fp16 mma m16n8k16)
#define BM 128
#define BN 128
#define KDIM 256
#define KC 32                    // K halves per smem chunk (= 64 B/row)
#define NKC (KDIM/KC)            // 8 chunks
#define HSTRIDE 40               // padded smem row stride in halves (LDSM conflict-free)
#define CHUNK_H (128*HSTRIDE)
#define SMEM_BYTES (4*CHUNK_H*2) // A0,A1,B0,B1 = 40960 B

// ---------------- static scratch ----------------
__device__ __align__(16) __half g_hrh[(size_t)NMAX * RREL * HDIM];  // relation blocks, fp16
__device__ __align__(16) float  g_root[(size_t)NMAX * HDIM];        // root block, fp32
__device__ __align__(16) float  g_h1[(size_t)NMAX * HDIM];
__device__ __align__(16) float  g_h2[(size_t)NMAX * HDIM];
__device__ __align__(16) __half g_arth[(size_t)NMAX * HDIM];        // fp16 activations (GEMM A)
__device__ __align__(16) float  g_relagg[(size_t)NMAX * HDIM];
__device__ __align__(16) __half g_wcat[(size_t)(9*HDIM) * KDIM];    // B K-major fp16
__device__ float g_projrel[RREL * HDIM];
__device__ float g_sc[NMAX * 9];
__device__ float g_score[EMAX];    // CSR-ordered leaky scores
__device__ int   g_rbb[EMAX];      // CSR-ordered src*8+et
__device__ int   g_dn[EMAX];       // CSR-ordered dst node
__device__ int   g_deg[NMAX];
__device__ int   g_rowptr[NMAX + 1];
__device__ int   g_cursor[NMAX];
__device__ int   g_cnt[NMAX * RREL];

// ---------------- helpers ----------------
__device__ __forceinline__ uint32_t smem_u32(const void* p) {
    uint32_t a;
    asm("{ .reg .u64 t; cvta.to.shared.u64 t, %1; cvt.u32.u64 %0, t; }" : "=r"(a) : "l"(p));
    return a;
}
__device__ __forceinline__ void cp_async16(uint32_t dst, const void* src, int src_sz) {
    asm volatile("cp.async.ca.shared.global [%0], [%1], 16, %2;"
                 :: "r"(dst), "l"(src), "r"(src_sz) : "memory");
}
__device__ __forceinline__ void ldsm_x4(uint32_t& r0, uint32_t& r1, uint32_t& r2, uint32_t& r3,
                                        uint32_t addr) {
    asm volatile("ldmatrix.sync.aligned.m8n8.x4.shared.b16 {%0,%1,%2,%3}, [%4];"
                 : "=r"(r0), "=r"(r1), "=r"(r2), "=r"(r3) : "r"(addr));
}
__device__ __forceinline__ void mma_f16(float& d0, float& d1, float& d2, float& d3,
                                        uint32_t a0, uint32_t a1, uint32_t a2, uint32_t a3,
                                        uint32_t b0, uint32_t b1) {
    asm volatile(
        "mma.sync.aligned.m16n8k16.row.col.f32.f16.f16.f32 "
        "{%0,%1,%2,%3}, {%4,%5,%6,%7}, {%8,%9}, {%0,%1,%2,%3};"
        : "+f"(d0), "+f"(d1), "+f"(d2), "+f"(d3)
        : "r"(a0), "r"(a1), "r"(a2), "r"(a3), "r"(b0), "r"(b1));
}

// ---------------- prep kernels ----------------
__global__ void k_zero() {
    int i = blockIdx.x * blockDim.x + threadIdx.x;
    if (i < NMAX) g_deg[i] = 0;
    if (i < NMAX * RREL) g_cnt[i] = 0;
}
__global__ void k_zsc(int n9) {
    int i = blockIdx.x * blockDim.x + threadIdx.x;
    if (i < n9) g_sc[i] = 0.f;
}
__global__ void k_degcnt(const int* __restrict__ dst, const int* __restrict__ et, int E) {
    int e = blockIdx.x * blockDim.x + threadIdx.x;
    if (e < E) {
        int d = dst[e];
        atomicAdd(&g_deg[d], 1);
        atomicAdd(&g_cnt[d * RREL + et[e]], 1);
    }
}
__global__ void k_scan(int n) {
    __shared__ int part[1024];
    int t = threadIdx.x;
    int per = (n + 1023) >> 10;
    int base = t * per;
    int s = 0;
    for (int i = 0; i < per; i++) { int idx = base + i; if (idx < n) s += g_deg[idx]; }
    part[t] = s; __syncthreads();
    for (int off = 1; off < 1024; off <<= 1) {
        int v = (t >= off) ? part[t - off] : 0;
        __syncthreads(); part[t] += v; __syncthreads();
    }
    int run = (t > 0) ? part[t - 1] : 0;
    for (int i = 0; i < per; i++) {
        int idx = base + i;
        if (idx < n) { g_rowptr[idx] = run; g_cursor[idx] = run; run += g_deg[idx]; }
    }
    if (t == 1023) g_rowptr[n] = part[1023];
}
// CSR fill: store src*8+et and dst per CSR slot
__global__ void k_fill(const int* __restrict__ src, const int* __restrict__ dst,
                       const int* __restrict__ et, int E) {
    int e = blockIdx.x * blockDim.x + threadIdx.x;
    if (e < E) {
        int d = dst[e];
        int p = atomicAdd(&g_cursor[d], 1);
        g_rbb[p] = src[e] * RREL + et[e];
        g_dn[p]  = d;
    }
}
__global__ void k_projrel(const float* __restrict__ re, const float* __restrict__ w,
                          const float* __restrict__ b) {
    int r = blockIdx.x, c = threadIdx.x;
    float s = b[c];
    for (int k = 0; k < HDIM; k++) s += re[r * HDIM + k] * w[k * HDIM + c];
    g_projrel[r * HDIM + c] = s;
}
__global__ void k_relagg() {
    int node = blockIdx.x, c = threadIdx.x;
    __shared__ float cc[RREL];
    if (c < RREL) cc[c] = (float)g_cnt[node * RREL + c];
    __syncthreads();
    float s = 0.f;
#pragma unroll
    for (int r = 0; r < RREL; r++) s += cc[r] * g_projrel[r * HDIM + c];
    g_relagg[(size_t)node * HDIM + c] = s;
}
// transpose weights K-major fp16: g_wcat[n*256 + k] = h(W[k][n]), n = j*dob + c
__global__ void k_repackT(const float* __restrict__ Wr, const float* __restrict__ Wo, int dob) {
    __shared__ float t[32][33];
    int j = blockIdx.z;
    int k0 = blockIdx.y * 32, c0 = blockIdx.x * 32;
    const float* W = (j < RREL) ? Wr + (size_t)j * KDIM * dob : Wo;
    for (int r = threadIdx.y; r < 32; r += 8)
        t[r][threadIdx.x] = W[(size_t)(k0 + r) * dob + c0 + threadIdx.x];
    __syncthreads();
    for (int r = threadIdx.y; r < 32; r += 8) {
        int n = j * dob + c0 + r;
        g_wcat[(size_t)n * KDIM + k0 + threadIdx.x] = __float2half_rn(t[threadIdx.x][r]);
    }
}
__global__ void k_tohalf(const float* __restrict__ in, __half* __restrict__ out, int n4) {
    int i = blockIdx.x * blockDim.x + threadIdx.x;
    if (i >= n4) return;
    float4 v = ((const float4*)in)[i];
    ((__half2*)out)[i * 2]     = __floats2half2_rn(v.x, v.y);
    ((__half2*)out)[i * 2 + 1] = __floats2half2_rn(v.z, v.w);
}

// ---------------- fp16 mma GEMM (ldmatrix fragments) + fused attention-dot ----------------
__global__ __launch_bounds__(256, 2)
void k_mma(const __half* __restrict__ A, __half* __restrict__ Ch, float* __restrict__ Cr,
           int M, int dob,
           const float* __restrict__ asrc, const float* __restrict__ adst) {
    extern __shared__ __half sm[];
    __half* sA[2] = { sm,               sm + CHUNK_H };
    __half* sB[2] = { sm + 2 * CHUNK_H, sm + 3 * CHUNK_H };

    int tid  = threadIdx.x;
    int wid  = tid >> 5, lane = tid & 31;
    int wm   = wid >> 1;
    int wn   = wid & 1;
    int bm   = blockIdx.y * BM, bn = blockIdx.x * BN;
    int lq   = lane >> 2;
    int lr   = lane & 3;

    float acc[2][8][4];
#pragma unroll
    for (int mt = 0; mt < 2; mt++)
#pragma unroll
        for (int nt = 0; nt < 8; nt++)
#pragma unroll
            for (int i = 0; i < 4; i++) acc[mt][nt][i] = 0.f;

    uint32_t sAb[2] = { smem_u32(sA[0]), smem_u32(sA[1]) };
    uint32_t sBb[2] = { smem_u32(sB[0]), smem_u32(sB[1]) };

    int lrow = tid >> 1;          // 0..127
    int lseg = (tid & 1) * 16;    // 0 or 16 halves
    int asz  = (bm + lrow < M) ? 16 : 0;

    auto load_chunk = [&](int buf, int kc) {
        int c0 = kc * KC;
        const __half* ga = A + (size_t)(bm + lrow) * KDIM + c0 + lseg;
        const __half* gb = g_wcat + (size_t)(bn + lrow) * KDIM + c0 + lseg;
        uint32_t off = (uint32_t)(lrow * HSTRIDE + lseg) * 2u;
        cp_async16(sAb[buf] + off,      ga,     asz);
        cp_async16(sAb[buf] + off + 16, ga + 8, asz);
        cp_async16(sBb[buf] + off,      gb,     16);
        cp_async16(sBb[buf] + off + 16, gb + 8, 16);
        asm volatile("cp.async.commit_group;" ::: "memory");
    };

    // ldmatrix lane addressing (byte offsets within a chunk buffer)
    // A, tile mt: rows wm*32+mt*16+(lane&15), col-group (lane>>4)*8 halves
    uint32_t aoff0 = (uint32_t)((wm * 32 + (lane & 15)) * HSTRIDE + (lane >> 4) * 8) * 2u;
    uint32_t aoff1 = aoff0 + (uint32_t)(16 * HSTRIDE) * 2u;
    // B, tile pair ntp: matrices (n0-7,k0-7),(n0-7,k8-15),(n8-15,k0-7),(n8-15,k8-15)
    int bk   = lane >> 3;                      // 0..3
    int bnl  = lane - 8 * ((bk + 1) >> 1);     // n-lane within 16-row pair block
    int bc   = (bk & 1) * 8;                   // k half-offset 0 or 8
    uint32_t boff = (uint32_t)((wn * 64 + bnl) * HSTRIDE + bc) * 2u;

    load_chunk(0, 0);

    for (int kc = 0; kc < NKC; kc++) {
        int buf = kc & 1;
        if (kc + 1 < NKC) {
            load_chunk(buf ^ 1, kc + 1);
            asm volatile("cp.async.wait_group 1;" ::: "memory");
        } else {
            asm volatile("cp.async.wait_group 0;" ::: "memory");
        }
        __syncthreads();

#pragma unroll
        for (int ks = 0; ks < 2; ks++) {
            uint32_t kofs = (uint32_t)(ks * 16) * 2u;   // 16 halves = 32 B
            uint32_t afr[2][4];
            ldsm_x4(afr[0][0], afr[0][1], afr[0][2], afr[0][3], sAb[buf] + aoff0 + kofs);
            ldsm_x4(afr[1][0], afr[1][1], afr[1][2], afr[1][3], sAb[buf] + aoff1 + kofs);
            uint32_t bfr[8][2];
#pragma unroll
            for (int ntp = 0; ntp < 4; ntp++)
                ldsm_x4(bfr[2*ntp][0], bfr[2*ntp][1], bfr[2*ntp+1][0], bfr[2*ntp+1][1],
                        sBb[buf] + boff + (uint32_t)(ntp * 16 * HSTRIDE) * 2u + kofs);
#pragma unroll
            for (int mt = 0; mt < 2; mt++)
#pragma unroll
                for (int nt = 0; nt < 8; nt++)
                    mma_f16(acc[mt][nt][0], acc[mt][nt][1], acc[mt][nt][2], acc[mt][nt][3],
                            afr[mt][0], afr[mt][1], afr[mt][2], afr[mt][3],
                            bfr[nt][0], bfr[nt][1]);
        }
        __syncthreads();
    }

    // fused attention-dot + split store
    int j    = bn / dob;               // relation slot (8 = root)
    int cbas = bn - j * dob;
    const float* att = (j < RREL) ? asrc : adst;
    bool isroot = (j >= RREL);

#pragma unroll
    for (int mt = 0; mt < 2; mt++) {
        int r0 = bm + wm * 32 + mt * 16 + lq;
        float s0 = 0.f, s1 = 0.f;
#pragma unroll
        for (int nt = 0; nt < 8; nt++) {
            int col = cbas + wn * 64 + nt * 8 + 2 * lr;
            float a0 = att[col], a1 = att[col + 1];
            s0 += acc[mt][nt][0] * a0 + acc[mt][nt][1] * a1;
            s1 += acc[mt][nt][2] * a0 + acc[mt][nt][3] * a1;
            if (isroot) {
                if (r0 < M)
                    *(float2*)(Cr + (size_t)r0 * dob + col) =
                        make_float2(acc[mt][nt][0], acc[mt][nt][1]);
                if (r0 + 8 < M)
                    *(float2*)(Cr + (size_t)(r0 + 8) * dob + col) =
                        make_float2(acc[mt][nt][2], acc[mt][nt][3]);
            } else {
                if (r0 < M)
                    *(__half2*)(Ch + ((size_t)r0 * RREL + j) * dob + col) =
                        __floats2half2_rn(acc[mt][nt][0], acc[mt][nt][1]);
                if (r0 + 8 < M)
                    *(__half2*)(Ch + ((size_t)(r0 + 8) * RREL + j) * dob + col) =
                        __floats2half2_rn(acc[mt][nt][2], acc[mt][nt][3]);
            }
        }
        s0 += __shfl_xor_sync(0xffffffffu, s0, 1);
        s0 += __shfl_xor_sync(0xffffffffu, s0, 2);
        s1 += __shfl_xor_sync(0xffffffffu, s1, 1);
        s1 += __shfl_xor_sync(0xffffffffu, s1, 2);
        if (lr == 0) {
            if (r0 < M)     atomicAdd(&g_sc[r0 * 9 + j], s0);
            if (r0 + 8 < M) atomicAdd(&g_sc[(r0 + 8) * 9 + j], s1);
        }
    }
}

// ---------------- edge scores, CSR-ordered ----------------
__global__ void k_score(int E) {
    int p = blockIdx.x * blockDim.x + threadIdx.x;
    if (p >= E) return;
    int rbb = g_rbb[p];
    int dn  = g_dn[p];
    float s = g_sc[rbb + (rbb >> 3)] + g_sc[dn * 9 + 8];
    g_score[p] = (s > 0.f) ? s : 0.2f * s;
}

// ---------------- warp-per-node softmax aggregation + epilogue ----------------
// NV=2: dob=256, hidden layers. NV=1: dob=128, final layer.
template <int NV>
__global__ void k_agg(const __half* __restrict__ hrh, const float* __restrict__ root,
                      const float* __restrict__ h_in,
                      float* __restrict__ h_out, __half* __restrict__ arth, int n) {
    int gw = (blockIdx.x * blockDim.x + threadIdx.x) >> 5;
    int lane = threadIdx.x & 31;
    if (gw >= n) return;
    const int dob = NV * 128;
    int node = gw;
    int beg = g_rowptr[node];
    int deg = g_rowptr[node + 1] - beg;

    float accA[4 * NV], accB[4 * NV];
#pragma unroll
    for (int i = 0; i < 4 * NV; i++) { accA[i] = 0.f; accB[i] = 0.f; }

    if (deg > 0) {
        float m = -1e30f;
        for (int i = lane; i < deg; i += 32)
            m = fmaxf(m, g_score[beg + i]);
#pragma unroll
        for (int o = 16; o; o >>= 1) m = fmaxf(m, __shfl_xor_sync(0xffffffffu, m, o));

        float dsum = 0.f;
        for (int base = 0; base < deg; base += 32) {
            int i = base + lane;
            float wv = 0.f; int rb = 0;
            if (i < deg) {
                wv = __expf(g_score[beg + i] - m);
                rb = g_rbb[beg + i] * dob;
            }
            dsum += wv;
            int cnt = min(32, deg - base);
            int jj = 0;
            for (; jj + 1 < cnt; jj += 2) {
                float w0 = __shfl_sync(0xffffffffu, wv, jj);
                int   r0 = __shfl_sync(0xffffffffu, rb, jj);
                float w1 = __shfl_sync(0xffffffffu, wv, jj + 1);
                int   r1 = __shfl_sync(0xffffffffu, rb, jj + 1);
                if (NV == 2) {
                    uint4 v0 = ((const uint4*)(hrh + r0))[lane];
                    uint4 v1 = ((const uint4*)(hrh + r1))[lane];
                    float2 f;
                    f = __half22float2(*(__half2*)&v0.x); accA[0] += w0*f.x; accA[1] += w0*f.y;
                    f = __half22float2(*(__half2*)&v0.y); accA[2] += w0*f.x; accA[3] += w0*f.y;
                    f = __half22float2(*(__half2*)&v0.z); accA[4] += w0*f.x; accA[5] += w0*f.y;
                    f = __half22float2(*(__half2*)&v0.w); accA[6] += w0*f.x; accA[7] += w0*f.y;
                    f = __half22float2(*(__half2*)&v1.x); accB[0] += w1*f.x; accB[1] += w1*f.y;
                    f = __half22float2(*(__half2*)&v1.y); accB[2] += w1*f.x; accB[3] += w1*f.y;
                    f = __half22float2(*(__half2*)&v1.z); accB[4] += w1*f.x; accB[5] += w1*f.y;
                    f = __half22float2(*(__half2*)&v1.w); accB[6] += w1*f.x; accB[7] += w1*f.y;
                } else {
                    uint2 v0 = ((const uint2*)(hrh + r0))[lane];
                    uint2 v1 = ((const uint2*)(hrh + r1))[lane];
                    float2 f;
                    f = __half22float2(*(__half2*)&v0.x); accA[0] += w0*f.x; accA[1] += w0*f.y;
                    f = __half22float2(*(__half2*)&v0.y); accA[2] += w0*f.x; accA[3] += w0*f.y;
                    f = __half22float2(*(__half2*)&v1.x); accB[0] += w1*f.x; accB[1] += w1*f.y;
                    f = __half22float2(*(__half2*)&v1.y); accB[2] += w1*f.x; accB[3] += w1*f.y;
                }
            }
            if (jj < cnt) {
                float w0 = __shfl_sync(0xffffffffu, wv, jj);
                int   r0 = __shfl_sync(0xffffffffu, rb, jj);
                if (NV == 2) {
                    uint4 v0 = ((const uint4*)(hrh + r0))[lane];
                    float2 f;
                    f = __half22float2(*(__half2*)&v0.x); accA[0] += w0*f.x; accA[1] += w0*f.y;
                    f = __half22float2(*(__half2*)&v0.y); accA[2] += w0*f.x; accA[3] += w0*f.y;
                    f = __half22float2(*(__half2*)&v0.z); accA[4] += w0*f.x; accA[5] += w0*f.y;
                    f = __half22float2(*(__half2*)&v0.w); accA[6] += w0*f.x; accA[7] += w0*f.y;
                } else {
                    uint2 v0 = ((const uint2*)(hrh + r0))[lane];
                    float2 f;
                    f = __half22float2(*(__half2*)&v0.x); accA[0] += w0*f.x; accA[1] += w0*f.y;
                    f = __half22float2(*(__half2*)&v0.y); accA[2] += w0*f.x; accA[3] += w0*f.y;
                }
            }
        }
#pragma unroll
        for (int o = 16; o; o >>= 1) dsum += __shfl_xor_sync(0xffffffffu, dsum, o);
        float inv = 1.f / dsum;
#pragma unroll
        for (int i = 0; i < 4 * NV; i++) accA[i] = (accA[i] + accB[i]) * inv;
    }

    const float4* rootp = (const float4*)(root + (size_t)node * dob);
    if (NV == 1) {
        float4 r = rootp[lane];
        r.x += accA[0]; r.y += accA[1]; r.z += accA[2]; r.w += accA[3];
        ((float4*)(h_out + (size_t)node * dob))[lane] = r;
    } else {
        const float4* rap = (const float4*)(g_relagg + (size_t)node * HDIM);
        const float4* hip = (const float4*)(h_in + (size_t)node * dob);
        float4* hop = (float4*)(h_out + (size_t)node * dob);
        __half2* arp = (__half2*)(arth + (size_t)node * dob);
#pragma unroll
        for (int q = 0; q < 2; q++) {
            int li = lane * 2 + q;
            float4 r = rootp[li], ra = rap[li], hi = hip[li];
            float4 o;
            o.x = hi.x + fmaxf(r.x + accA[q*4+0] + ra.x, 0.f);
            o.y = hi.y + fmaxf(r.y + accA[q*4+1] + ra.y, 0.f);
            o.z = hi.z + fmaxf(r.z + accA[q*4+2] + ra.z, 0.f);
            o.w = hi.w + fmaxf(r.w + accA[q*4+3] + ra.w, 0.f);
            hop[li] = o;
            arp[li * 2]     = __floats2half2_rn(o.x, o.y);
            arp[li * 2 + 1] = __floats2half2_rn(o.z, o.w);
        }
    }
}

// ---------------- launcher ----------------
extern "C" void kernel_launch(void* const* d_in, const int* in_sizes, int n_in,
                              void* d_out, int out_size) {
    const float* x    = (const float*)d_in[0];
    const int*   ei   = (const int*)  d_in[1];
    const int*   et   = (const int*)  d_in[2];
    const float* remb = (const float*)d_in[3];
    const float* rpw  = (const float*)d_in[4];
    const float* rpb  = (const float*)d_in[5];
    const float* Wr[3] = {(const float*)d_in[6],  (const float*)d_in[10], (const float*)d_in[14]};
    const float* Wo[3] = {(const float*)d_in[7],  (const float*)d_in[11], (const float*)d_in[15]};
    const float* Av[3] = {(const float*)d_in[8],  (const float*)d_in[12], (const float*)d_in[16]};
    const float* Ad[3] = {(const float*)d_in[9],  (const float*)d_in[13], (const float*)d_in[17]};

    int N = in_sizes[0] / HDIM;     // 20000
    int E = in_sizes[2];            // 400000
    const int* srcp = ei;
    const int* dstp = ei + E;

    float *root, *h1, *h2;
    __half *arth, *hrh;
    cudaGetSymbolAddress((void**)&hrh,  g_hrh);
    cudaGetSymbolAddress((void**)&root, g_root);
    cudaGetSymbolAddress((void**)&h1,   g_h1);
    cudaGetSymbolAddress((void**)&h2,   g_h2);
    cudaGetSymbolAddress((void**)&arth, g_arth);

    cudaFuncSetAttribute(k_mma, cudaFuncAttributeMaxDynamicSharedMemorySize, SMEM_BYTES);

    // ---- graph prep (layer-invariant) ----
    k_zero<<<(NMAX * RREL + 255) / 256, 256>>>();
    k_degcnt<<<(E + 255) / 256, 256>>>(dstp, et, E);
    k_scan<<<1, 1024>>>(N);
    k_fill<<<(E + 255) / 256, 256>>>(srcp, dstp, et, E);
    k_projrel<<<RREL, HDIM>>>(remb, rpw, rpb);
    k_relagg<<<N, HDIM>>>();
    int n4 = N * HDIM / 4;
    k_tohalf<<<(n4 + 255) / 256, 256>>>(x, arth, n4);

    // ---- three RGAT layers ----
    const float* hin = x;
    for (int l = 0; l < 3; l++) {
        int dob = (l == 2) ? ODIM : HDIM;
        int pitch = 9 * dob;

        dim3 gt(dob / 32, KDIM / 32, 9);
        k_repackT<<<gt, dim3(32, 8)>>>(Wr[l], Wo[l], dob);
        k_zsc<<<(N * 9 + 255) / 256, 256>>>(N * 9);

        dim3 g(pitch / BN, (N + BM - 1) / BM);
        k_mma<<<g, 256, SMEM_BYTES>>>(arth, hrh, root, N, dob, Av[l], Ad[l]);

        k_score<<<(E + 255) / 256, 256>>>(E);

        float* hout = (l == 0) ? h1 : (l == 1) ? h2 : (float*)d_out;
        int wblocks = (N * 32 + 255) / 256;
        if (l == 2)
            k_agg<1><<<wblocks, 256>>>(hrh, root, hin, hout, arth, N);
        else
            k_agg<2><<<wblocks, 256>>>(hrh, root, hin, hout, arth, N);
        hin = hout;
    }
}

// round 16
// speedup vs baseline: 1.0596x; 1.0195x over previous
#include <cuda_runtime.h>
#include <cuda_fp16.h>
#include <cstdint>
#include <math.h>

// ---------------- problem constants ----------------
#define NMAX   20000
#define EMAX   400000
#define RREL   8
#define HDIM   256
#define ODIM   128

// GEMM tiling (fp16 mma m16n8k16)
#define BM 128
#define BN 128
#define KDIM 256
#define KC 32                    // K halves per smem chunk (= 64 B/row)
#define NKC (KDIM/KC)            // 8 chunks
#define HSTRIDE 40               // padded smem row stride in halves (LDSM conflict-free)
#define CHUNK_H (128*HSTRIDE)
#define SMEM_BYTES (4*CHUNK_H*2) // A0,A1,B0,B1 = 40960 B
#define WSLOT ((size_t)(9*HDIM)*KDIM)   // per-layer g_wcat slot (halves)

// ---------------- static scratch ----------------
__device__ __align__(16) __half g_hrh[(size_t)NMAX * RREL * HDIM];  // relation blocks, fp16
__device__ __align__(16) float  g_root[(size_t)NMAX * HDIM];        // root block, fp32
__device__ __align__(16) float  g_h1[(size_t)NMAX * HDIM];
__device__ __align__(16) float  g_h2[(size_t)NMAX * HDIM];
__device__ __align__(16) __half g_arth[(size_t)NMAX * HDIM];        // fp16 activations (GEMM A)
__device__ __align__(16) float  g_relagg[(size_t)NMAX * HDIM];
__device__ __align__(16) __half g_wcat[3 * WSLOT];                  // B K-major fp16, 3 layers
__device__ float g_projrel[RREL * HDIM];
__device__ float g_sc[NMAX * 9];
__device__ float g_score[EMAX];    // CSR-ordered leaky scores
__device__ int   g_rbb[EMAX];      // CSR-ordered src*8+et
__device__ int   g_dn[EMAX];       // CSR-ordered dst node
__device__ int   g_deg[NMAX];
__device__ int   g_rowptr[NMAX + 1];
__device__ int   g_cursor[NMAX];
__device__ int   g_cnt[NMAX * RREL];

// ---------------- helpers ----------------
__device__ __forceinline__ uint32_t smem_u32(const void* p) {
    uint32_t a;
    asm("{ .reg .u64 t; cvta.to.shared.u64 t, %1; cvt.u32.u64 %0, t; }" : "=r"(a) : "l"(p));
    return a;
}
__device__ __forceinline__ void cp_async16(uint32_t dst, const void* src, int src_sz) {
    asm volatile("cp.async.ca.shared.global [%0], [%1], 16, %2;"
                 :: "r"(dst), "l"(src), "r"(src_sz) : "memory");
}
__device__ __forceinline__ void ldsm_x4(uint32_t& r0, uint32_t& r1, uint32_t& r2, uint32_t& r3,
                                        uint32_t addr) {
    asm volatile("ldmatrix.sync.aligned.m8n8.x4.shared.b16 {%0,%1,%2,%3}, [%4];"
                 : "=r"(r0), "=r"(r1), "=r"(r2), "=r"(r3) : "r"(addr));
}
__device__ __forceinline__ void mma_f16(float& d0, float& d1, float& d2, float& d3,
                                        uint32_t a0, uint32_t a1, uint32_t a2, uint32_t a3,
                                        uint32_t b0, uint32_t b1) {
    asm volatile(
        "mma.sync.aligned.m16n8k16.row.col.f32.f16.f16.f32 "
        "{%0,%1,%2,%3}, {%4,%5,%6,%7}, {%8,%9}, {%0,%1,%2,%3};"
        : "+f"(d0), "+f"(d1), "+f"(d2), "+f"(d3)
        : "r"(a0), "r"(a1), "r"(a2), "r"(a3), "r"(b0), "r"(b1));
}

// ---------------- prep kernels ----------------
__global__ void k_zero() {
    int i = blockIdx.x * blockDim.x + threadIdx.x;
    if (i < NMAX) g_deg[i] = 0;
    if (i < NMAX * RREL) g_cnt[i] = 0;
}
__global__ void k_degcnt(const int* __restrict__ dst, const int* __restrict__ et, int E) {
    int e = blockIdx.x * blockDim.x + threadIdx.x;
    if (e < E) {
        int d = dst[e];
        atomicAdd(&g_deg[d], 1);
        atomicAdd(&g_cnt[d * RREL + et[e]], 1);
    }
}
__global__ void k_scan(int n) {
    __shared__ int part[1024];
    int t = threadIdx.x;
    int per = (n + 1023) >> 10;
    int base = t * per;
    int s = 0;
    for (int i = 0; i < per; i++) { int idx = base + i; if (idx < n) s += g_deg[idx]; }
    part[t] = s; __syncthreads();
    for (int off = 1; off < 1024; off <<= 1) {
        int v = (t >= off) ? part[t - off] : 0;
        __syncthreads(); part[t] += v; __syncthreads();
    }
    int run = (t > 0) ? part[t - 1] : 0;
    for (int i = 0; i < per; i++) {
        int idx = base + i;
        if (idx < n) { g_rowptr[idx] = run; g_cursor[idx] = run; run += g_deg[idx]; }
    }
    if (t == 1023) g_rowptr[n] = part[1023];
}
// CSR fill: store src*8+et and dst per CSR slot
__global__ void k_fill(const int* __restrict__ src, const int* __restrict__ dst,
                       const int* __restrict__ et, int E) {
    int e = blockIdx.x * blockDim.x + threadIdx.x;
    if (e < E) {
        int d = dst[e];
        int p = atomicAdd(&g_cursor[d], 1);
        g_rbb[p] = src[e] * RREL + et[e];
        g_dn[p]  = d;
    }
}
__global__ void k_projrel(const float* __restrict__ re, const float* __restrict__ w,
                          const float* __restrict__ b) {
    int r = blockIdx.x, c = threadIdx.x;
    float s = b[c];
    for (int k = 0; k < HDIM; k++) s += re[r * HDIM + k] * w[k * HDIM + c];
    g_projrel[r * HDIM + c] = s;
}
__global__ void k_relagg() {
    int node = blockIdx.x, c = threadIdx.x;
    __shared__ float cc[RREL];
    if (c < RREL) cc[c] = (float)g_cnt[node * RREL + c];
    __syncthreads();
    float s = 0.f;
#pragma unroll
    for (int r = 0; r < RREL; r++) s += cc[r] * g_projrel[r * HDIM + c];
    g_relagg[(size_t)node * HDIM + c] = s;
}
// transpose+round weights for ALL 3 layers: z = layer*9 + j
__global__ void k_repackT3(const float* __restrict__ Wr0, const float* __restrict__ Wo0,
                           const float* __restrict__ Wr1, const float* __restrict__ Wo1,
                           const float* __restrict__ Wr2, const float* __restrict__ Wo2) {
    __shared__ float t[32][33];
    int z = blockIdx.z;
    int l = z / 9, j = z - l * 9;
    int dob = (l == 2) ? ODIM : HDIM;
    int k0 = blockIdx.y * 32, c0 = blockIdx.x * 32;
    if (c0 >= dob) return;
    const float* Wr = (l == 0) ? Wr0 : (l == 1) ? Wr1 : Wr2;
    const float* Wo = (l == 0) ? Wo0 : (l == 1) ? Wo1 : Wo2;
    const float* W = (j < RREL) ? Wr + (size_t)j * KDIM * dob : Wo;
    for (int r = threadIdx.y; r < 32; r += 8)
        t[r][threadIdx.x] = W[(size_t)(k0 + r) * dob + c0 + threadIdx.x];
    __syncthreads();
    __half* wc = g_wcat + (size_t)l * WSLOT;
    for (int r = threadIdx.y; r < 32; r += 8) {
        int n = j * dob + c0 + r;
        wc[(size_t)n * KDIM + k0 + threadIdx.x] = __float2half_rn(t[threadIdx.x][r]);
    }
}
// fp32 -> fp16 activations; also zero g_sc for layer 0 (i < n9)
__global__ void k_tohalf(const float* __restrict__ in, __half* __restrict__ out,
                         int n4, int n9) {
    int i = blockIdx.x * blockDim.x + threadIdx.x;
    if (i < n9) g_sc[i] = 0.f;
    if (i >= n4) return;
    float4 v = ((const float4*)in)[i];
    ((__half2*)out)[i * 2]     = __floats2half2_rn(v.x, v.y);
    ((__half2*)out)[i * 2 + 1] = __floats2half2_rn(v.z, v.w);
}

// ---------------- fp16 mma GEMM (ldmatrix fragments) + fused attention-dot ----------------
__global__ __launch_bounds__(256, 2)
void k_mma(const __half* __restrict__ A, const __half* __restrict__ W,
           __half* __restrict__ Ch, float* __restrict__ Cr,
           int M, int dob,
           const float* __restrict__ asrc, const float* __restrict__ adst) {
    extern __shared__ __half sm[];
    __half* sA[2] = { sm,               sm + CHUNK_H };
    __half* sB[2] = { sm + 2 * CHUNK_H, sm + 3 * CHUNK_H };

    int tid  = threadIdx.x;
    int wid  = tid >> 5, lane = tid & 31;
    int wm   = wid >> 1;
    int wn   = wid & 1;
    int bm   = blockIdx.y * BM, bn = blockIdx.x * BN;
    int lq   = lane >> 2;
    int lr   = lane & 3;

    float acc[2][8][4];
#pragma unroll
    for (int mt = 0; mt < 2; mt++)
#pragma unroll
        for (int nt = 0; nt < 8; nt++)
#pragma unroll
            for (int i = 0; i < 4; i++) acc[mt][nt][i] = 0.f;

    uint32_t sAb[2] = { smem_u32(sA[0]), smem_u32(sA[1]) };
    uint32_t sBb[2] = { smem_u32(sB[0]), smem_u32(sB[1]) };

    int lrow = tid >> 1;          // 0..127
    int lseg = (tid & 1) * 16;    // 0 or 16 halves
    int asz  = (bm + lrow < M) ? 16 : 0;

    auto load_chunk = [&](int buf, int kc) {
        int c0 = kc * KC;
        const __half* ga = A + (size_t)(bm + lrow) * KDIM + c0 + lseg;
        const __half* gb = W + (size_t)(bn + lrow) * KDIM + c0 + lseg;
        uint32_t off = (uint32_t)(lrow * HSTRIDE + lseg) * 2u;
        cp_async16(sAb[buf] + off,      ga,     asz);
        cp_async16(sAb[buf] + off + 16, ga + 8, asz);
        cp_async16(sBb[buf] + off,      gb,     16);
        cp_async16(sBb[buf] + off + 16, gb + 8, 16);
        asm volatile("cp.async.commit_group;" ::: "memory");
    };

    // ldmatrix lane addressing (byte offsets within a chunk buffer)
    uint32_t aoff0 = (uint32_t)((wm * 32 + (lane & 15)) * HSTRIDE + (lane >> 4) * 8) * 2u;
    uint32_t aoff1 = aoff0 + (uint32_t)(16 * HSTRIDE) * 2u;
    int bk   = lane >> 3;
    int bnl  = lane - 8 * ((bk + 1) >> 1);
    int bc   = (bk & 1) * 8;
    uint32_t boff = (uint32_t)((wn * 64 + bnl) * HSTRIDE + bc) * 2u;

    load_chunk(0, 0);

    for (int kc = 0; kc < NKC; kc++) {
        int buf = kc & 1;
        if (kc + 1 < NKC) {
            load_chunk(buf ^ 1, kc + 1);
            asm volatile("cp.async.wait_group 1;" ::: "memory");
        } else {
            asm volatile("cp.async.wait_group 0;" ::: "memory");
        }
        __syncthreads();

#pragma unroll
        for (int ks = 0; ks < 2; ks++) {
            uint32_t kofs = (uint32_t)(ks * 16) * 2u;
            uint32_t afr[2][4];
            ldsm_x4(afr[0][0], afr[0][1], afr[0][2], afr[0][3], sAb[buf] + aoff0 + kofs);
            ldsm_x4(afr[1][0], afr[1][1], afr[1][2], afr[1][3], sAb[buf] + aoff1 + kofs);
            uint32_t bfr[8][2];
#pragma unroll
            for (int ntp = 0; ntp < 4; ntp++)
                ldsm_x4(bfr[2*ntp][0], bfr[2*ntp][1], bfr[2*ntp+1][0], bfr[2*ntp+1][1],
                        sBb[buf] + boff + (uint32_t)(ntp * 16 * HSTRIDE) * 2u + kofs);
#pragma unroll
            for (int mt = 0; mt < 2; mt++)
#pragma unroll
                for (int nt = 0; nt < 8; nt++)
                    mma_f16(acc[mt][nt][0], acc[mt][nt][1], acc[mt][nt][2], acc[mt][nt][3],
                            afr[mt][0], afr[mt][1], afr[mt][2], afr[mt][3],
                            bfr[nt][0], bfr[nt][1]);
        }
        __syncthreads();
    }

    // fused attention-dot + split store
    int j    = bn / dob;               // relation slot (8 = root)
    int cbas = bn - j * dob;
    const float* att = (j < RREL) ? asrc : adst;
    bool isroot = (j >= RREL);

#pragma unroll
    for (int mt = 0; mt < 2; mt++) {
        int r0 = bm + wm * 32 + mt * 16 + lq;
        float s0 = 0.f, s1 = 0.f;
#pragma unroll
        for (int nt = 0; nt < 8; nt++) {
            int col = cbas + wn * 64 + nt * 8 + 2 * lr;
            float a0 = att[col], a1 = att[col + 1];
            s0 += acc[mt][nt][0] * a0 + acc[mt][nt][1] * a1;
            s1 += acc[mt][nt][2] * a0 + acc[mt][nt][3] * a1;
            if (isroot) {
                if (r0 < M)
                    *(float2*)(Cr + (size_t)r0 * dob + col) =
                        make_float2(acc[mt][nt][0], acc[mt][nt][1]);
                if (r0 + 8 < M)
                    *(float2*)(Cr + (size_t)(r0 + 8) * dob + col) =
                        make_float2(acc[mt][nt][2], acc[mt][nt][3]);
            } else {
                if (r0 < M)
                    *(__half2*)(Ch + ((size_t)r0 * RREL + j) * dob + col) =
                        __floats2half2_rn(acc[mt][nt][0], acc[mt][nt][1]);
                if (r0 + 8 < M)
                    *(__half2*)(Ch + ((size_t)(r0 + 8) * RREL + j) * dob + col) =
                        __floats2half2_rn(acc[mt][nt][2], acc[mt][nt][3]);
            }
        }
        s0 += __shfl_xor_sync(0xffffffffu, s0, 1);
        s0 += __shfl_xor_sync(0xffffffffu, s0, 2);
        s1 += __shfl_xor_sync(0xffffffffu, s1, 1);
        s1 += __shfl_xor_sync(0xffffffffu, s1, 2);
        if (lr == 0) {
            if (r0 < M)     atomicAdd(&g_sc[r0 * 9 + j], s0);
            if (r0 + 8 < M) atomicAdd(&g_sc[(r0 + 8) * 9 + j], s1);
        }
    }
}

// ---------------- edge scores, CSR-ordered ----------------
__global__ void k_score(int E) {
    int p = blockIdx.x * blockDim.x + threadIdx.x;
    if (p >= E) return;
    int rbb = g_rbb[p];
    int dn  = g_dn[p];
    float s = g_sc[rbb + (rbb >> 3)] + g_sc[dn * 9 + 8];
    g_score[p] = (s > 0.f) ? s : 0.2f * s;
}

// ---------------- warp-per-node softmax aggregation + epilogue ----------------
// NV=2 additionally zeroes g_sc[node*9..+9) for the NEXT layer's k_mma atomics
// (g_sc was fully consumed by this layer's k_score).
template <int NV>
__global__ void k_agg(const __half* __restrict__ hrh, const float* __restrict__ root,
                      const float* __restrict__ h_in,
                      float* __restrict__ h_out, __half* __restrict__ arth, int n) {
    int gw = (blockIdx.x * blockDim.x + threadIdx.x) >> 5;
    int lane = threadIdx.x & 31;
    if (gw >= n) return;
    const int dob = NV * 128;
    int node = gw;
    int beg = g_rowptr[node];
    int deg = g_rowptr[node + 1] - beg;

    float accA[4 * NV], accB[4 * NV];
#pragma unroll
    for (int i = 0; i < 4 * NV; i++) { accA[i] = 0.f; accB[i] = 0.f; }

    if (deg > 0) {
        float m = -1e30f;
        for (int i = lane; i < deg; i += 32)
            m = fmaxf(m, g_score[beg + i]);
#pragma unroll
        for (int o = 16; o; o >>= 1) m = fmaxf(m, __shfl_xor_sync(0xffffffffu, m, o));

        float dsum = 0.f;
        for (int base = 0; base < deg; base += 32) {
            int i = base + lane;
            float wv = 0.f; int rb = 0;
            if (i < deg) {
                wv = __expf(g_score[beg + i] - m);
                rb = g_rbb[beg + i] * dob;
            }
            dsum += wv;
            int cnt = min(32, deg - base);
            int jj = 0;
            for (; jj + 1 < cnt; jj += 2) {
                float w0 = __shfl_sync(0xffffffffu, wv, jj);
                int   r0 = __shfl_sync(0xffffffffu, rb, jj);
                float w1 = __shfl_sync(0xffffffffu, wv, jj + 1);
                int   r1 = __shfl_sync(0xffffffffu, rb, jj + 1);
                if (NV == 2) {
                    uint4 v0 = ((const uint4*)(hrh + r0))[lane];
                    uint4 v1 = ((const uint4*)(hrh + r1))[lane];
                    float2 f;
                    f = __half22float2(*(__half2*)&v0.x); accA[0] += w0*f.x; accA[1] += w0*f.y;
                    f = __half22float2(*(__half2*)&v0.y); accA[2] += w0*f.x; accA[3] += w0*f.y;
                    f = __half22float2(*(__half2*)&v0.z); accA[4] += w0*f.x; accA[5] += w0*f.y;
                    f = __half22float2(*(__half2*)&v0.w); accA[6] += w0*f.x; accA[7] += w0*f.y;
                    f = __half22float2(*(__half2*)&v1.x); accB[0] += w1*f.x; accB[1] += w1*f.y;
                    f = __half22float2(*(__half2*)&v1.y); accB[2] += w1*f.x; accB[3] += w1*f.y;
                    f = __half22float2(*(__half2*)&v1.z); accB[4] += w1*f.x; accB[5] += w1*f.y;
                    f = __half22float2(*(__half2*)&v1.w); accB[6] += w1*f.x; accB[7] += w1*f.y;
                } else {
                    uint2 v0 = ((const uint2*)(hrh + r0))[lane];
                    uint2 v1 = ((const uint2*)(hrh + r1))[lane];
                    float2 f;
                    f = __half22float2(*(__half2*)&v0.x); accA[0] += w0*f.x; accA[1] += w0*f.y;
                    f = __half22float2(*(__half2*)&v0.y); accA[2] += w0*f.x; accA[3] += w0*f.y;
                    f = __half22float2(*(__half2*)&v1.x); accB[0] += w1*f.x; accB[1] += w1*f.y;
                    f = __half22float2(*(__half2*)&v1.y); accB[2] += w1*f.x; accB[3] += w1*f.y;
                }
            }
            if (jj < cnt) {
                float w0 = __shfl_sync(0xffffffffu, wv, jj);
                int   r0 = __shfl_sync(0xffffffffu, rb, jj);
                if (NV == 2) {
                    uint4 v0 = ((const uint4*)(hrh + r0))[lane];
                    float2 f;
                    f = __half22float2(*(__half2*)&v0.x); accA[0] += w0*f.x; accA[1] += w0*f.y;
                    f = __half22float2(*(__half2*)&v0.y); accA[2] += w0*f.x; accA[3] += w0*f.y;
                    f = __half22float2(*(__half2*)&v0.z); accA[4] += w0*f.x; accA[5] += w0*f.y;
                    f = __half22float2(*(__half2*)&v0.w); accA[6] += w0*f.x; accA[7] += w0*f.y;
                } else {
                    uint2 v0 = ((const uint2*)(hrh + r0))[lane];
                    float2 f;
                    f = __half22float2(*(__half2*)&v0.x); accA[0] += w0*f.x; accA[1] += w0*f.y;
                    f = __half22float2(*(__half2*)&v0.y); accA[2] += w0*f.x; accA[3] += w0*f.y;
                }
            }
        }
#pragma unroll
        for (int o = 16; o; o >>= 1) dsum += __shfl_xor_sync(0xffffffffu, dsum, o);
        float inv = 1.f / dsum;
#pragma unroll
        for (int i = 0; i < 4 * NV; i++) accA[i] = (accA[i] + accB[i]) * inv;
    }

    const float4* rootp = (const float4*)(root + (size_t)node * dob);
    if (NV == 1) {
        float4 r = rootp[lane];
        r.x += accA[0]; r.y += accA[1]; r.z += accA[2]; r.w += accA[3];
        ((float4*)(h_out + (size_t)node * dob))[lane] = r;
    } else {
        const float4* rap = (const float4*)(g_relagg + (size_t)node * HDIM);
        const float4* hip = (const float4*)(h_in + (size_t)node * dob);
        float4* hop = (float4*)(h_out + (size_t)node * dob);
        __half2* arp = (__half2*)(arth + (size_t)node * dob);
#pragma unroll
        for (int q = 0; q < 2; q++) {
            int li = lane * 2 + q;
            float4 r = rootp[li], ra = rap[li], hi = hip[li];
            float4 o;
            o.x = hi.x + fmaxf(r.x + accA[q*4+0] + ra.x, 0.f);
            o.y = hi.y + fmaxf(r.y + accA[q*4+1] + ra.y, 0.f);
            o.z = hi.z + fmaxf(r.z + accA[q*4+2] + ra.z, 0.f);
            o.w = hi.w + fmaxf(r.w + accA[q*4+3] + ra.w, 0.f);
            hop[li] = o;
            arp[li * 2]     = __floats2half2_rn(o.x, o.y);
            arp[li * 2 + 1] = __floats2half2_rn(o.z, o.w);
        }
        // zero score table for next layer's k_mma atomics
        if (lane < 9) g_sc[node * 9 + lane] = 0.f;
    }
}

// ---------------- launcher ----------------
extern "C" void kernel_launch(void* const* d_in, const int* in_sizes, int n_in,
                              void* d_out, int out_size) {
    const float* x    = (const float*)d_in[0];
    const int*   ei   = (const int*)  d_in[1];
    const int*   et   = (const int*)  d_in[2];
    const float* remb = (const float*)d_in[3];
    const float* rpw  = (const float*)d_in[4];
    const float* rpb  = (const float*)d_in[5];
    const float* Wr[3] = {(const float*)d_in[6],  (const float*)d_in[10], (const float*)d_in[14]};
    const float* Wo[3] = {(const float*)d_in[7],  (const float*)d_in[11], (const float*)d_in[15]};
    const float* Av[3] = {(const float*)d_in[8],  (const float*)d_in[12], (const float*)d_in[16]};
    const float* Ad[3] = {(const float*)d_in[9],  (const float*)d_in[13], (const float*)d_in[17]};

    int N = in_sizes[0] / HDIM;     // 20000
    int E = in_sizes[2];            // 400000
    const int* srcp = ei;
    const int* dstp = ei + E;

    float *root, *h1, *h2;
    __half *arth, *hrh, *wcat;
    cudaGetSymbolAddress((void**)&hrh,  g_hrh);
    cudaGetSymbolAddress((void**)&root, g_root);
    cudaGetSymbolAddress((void**)&h1,   g_h1);
    cudaGetSymbolAddress((void**)&h2,   g_h2);
    cudaGetSymbolAddress((void**)&arth, g_arth);
    cudaGetSymbolAddress((void**)&wcat, g_wcat);

    cudaFuncSetAttribute(k_mma, cudaFuncAttributeMaxDynamicSharedMemorySize, SMEM_BYTES);

    // ---- graph prep (layer-invariant) ----
    k_zero<<<(NMAX * RREL + 255) / 256, 256>>>();
    k_degcnt<<<(E + 255) / 256, 256>>>(dstp, et, E);
    k_scan<<<1, 1024>>>(N);
    k_fill<<<(E + 255) / 256, 256>>>(srcp, dstp, et, E);
    k_projrel<<<RREL, HDIM>>>(remb, rpw, rpb);
    k_relagg<<<N, HDIM>>>();
    dim3 gt(HDIM / 32, KDIM / 32, 27);
    k_repackT3<<<gt, dim3(32, 8)>>>(Wr[0], Wo[0], Wr[1], Wo[1], Wr[2], Wo[2]);
    int n4 = N * HDIM / 4;
    k_tohalf<<<(n4 + 255) / 256, 256>>>(x, arth, n4, N * 9);

    // ---- three RGAT layers: mma -> score -> agg ----
    const float* hin = x;
    for (int l = 0; l < 3; l++) {
        int dob = (l == 2) ? ODIM : HDIM;
        int pitch = 9 * dob;

        dim3 g(pitch / BN, (N + BM - 1) / BM);
        k_mma<<<g, 256, SMEM_BYTES>>>(arth, wcat + (size_t)l * WSLOT, hrh, root,
                                      N, dob, Av[l], Ad[l]);

        k_score<<<(E + 255) / 256, 256>>>(E);

        float* hout = (l == 0) ? h1 : (l == 1) ? h2 : (float*)d_out;
        int wblocks = (N * 32 + 255) / 256;
        if (l == 2)
            k_agg<1><<<wblocks, 256>>>(hrh, root, hin, hout, arth, N);
        else
            k_agg<2><<<wblocks, 256>>>(hrh, root, hin, hout, arth, N);
        hin = hout;
    }
}